// round 16
// baseline (speedup 1.0000x reference)
#include <cuda_runtime.h>
#include <cuda_fp16.h>
#include <math.h>
#include <stdint.h>

// Problem constants
#define DIMN  2048
#define BATCH 16384

// Tile constants (verified R10-R15)
#define BK    64
#define ROWB  144u                    // 128B data + 16B pad -> conflict-free LDSM
#define TILEB (128u * ROWB)           // 18432 B per 128x64 fp16 tile
#define NST   3
#define STAGEB (2u * TILEB)           // A + B single tiles = 36864
#define SMEM_GEMM (NST * STAGEB)      // 110592 B -> 2 CTAs/SM

// Convert sizes
#define NX (BATCH * DIMN)             // 33554432
#define N1 (1024 * DIMN)              // 2097152
#define N2 (512 * 1024)               // 524288
#define N3 (256 * 512)                // 131072
#define NREST (NX + N2 + 2 * N3)      // x + W2 + Wmu + Wlv

// ---------------------------------------------------------------------------
// Device scratch (static — no runtime allocs)
// ---------------------------------------------------------------------------
__device__ __align__(128) __half g_Dt   [DIMN * DIMN];   // Dt[m][kf]=D[kf][m]
__device__ __align__(128) __half g_Dm   [DIMN * DIMN];   // Dm[r][c] = D[r][c]
__device__ __align__(128) __half g_W1f  [1024 * DIMN];
__device__ __align__(128) __half g_A1f  [1024 * DIMN];
__device__ __align__(128) __half g_W1ef [1024 * DIMN];
__device__ __align__(128) __half g_x16  [BATCH * DIMN];
__device__ __align__(128) __half g_h1_16[BATCH * 1024];
__device__ __align__(128) __half g_h2_16[BATCH * 512];
__device__ __align__(128) __half g_W2f  [512 * 1024];
__device__ __align__(128) __half g_Wmlf [512 * 512];
__device__ __align__(128) float g_part[2 * 1024 * DIMN]; // split-K=2 partials
__device__ __align__(128) float g_costab[8192];          // cos(pi*q/4096)
__device__ float g_bml[512];
__device__ float g_bscale[DIMN];

static __device__ __forceinline__ uint32_t packh(float a, float b)
{
    __half2 t = __floats2half2_rn(a, b);
    return *reinterpret_cast<uint32_t*>(&t);
}

// ---------------------------------------------------------------------------
// Fused setup: cos table (8192) + band-scale (2048) + merged bias (512)
// ---------------------------------------------------------------------------
__global__ void setup_kernel(const float* __restrict__ fw,
                             const float* __restrict__ kptr,
                             const float* __restrict__ bmu,
                             const float* __restrict__ blv)
{
    int idx = blockIdx.x * blockDim.x + threadIdx.x;

    if (idx < 8192) {
        g_costab[idx] = cospif((float)idx * (1.0f / 4096.0f));
    } else if (idx < 8192 + DIMN) {
        int i2 = idx - 8192;
        const float kv = *kptr;
        float val = 1.0f;
        const double step = 2047.0 / 30.0;
        #pragma unroll 1
        for (int i = 0; i < 30; i++) {
            int s = (int)(step * (double)i);
            int e = (i == 29) ? 2047 : (int)(step * (double)(i + 1));
            if (i2 >= s && i2 < e) {
                float f;
                if (e <= 30) f = 1.0f + fw[i] * kv * (1.0f - (float)i / 30.0f);
                else         f = 1.0f - fw[i] * kv * (1.0f - (float)(i - 30) / 30.0f);
                val = f;
            }
        }
        g_bscale[i2] = val;
    } else if (idx < 8192 + DIMN + 512) {
        int i3 = idx - 8192 - DIMN;
        g_bml[i3] = (i3 < 256) ? bmu[i3] : blv[i3 - 256];
    }
}

// ---------------------------------------------------------------------------
// Build BOTH Dm and Dt via per-row Chebyshev recurrences (verified R15).
// ---------------------------------------------------------------------------
__global__ void build_D_kernel()
{
    int t = blockIdx.x * blockDim.x + threadIdx.x;   // < 2048*64
    int r  = t >> 6;
    int c0 = (t & 63) << 5;
    const float n0 = 0.022097086912079612f;  // sqrt(1/2048)
    const float n1 = 0.03125f;               // sqrt(2/2048)
    const float normR = (r == 0) ? n0 : n1;

    float pm = g_costab[((2 * c0 + 1) * r) & 8191];
    float cm = g_costab[((2 * c0 + 3) * r) & 8191];
    const float Km = 2.0f * g_costab[(2 * r) & 8191];
    float pt = g_costab[((2 * r + 1) * c0) & 8191];
    float ct = g_costab[((2 * r + 1) * (c0 + 1)) & 8191];
    const float Kt = 2.0f * g_costab[(2 * r + 1) & 8191];

    size_t rowoff = (size_t)r * DIMN;
    #pragma unroll
    for (int chunk = 0; chunk < 4; chunk++) {
        uint32_t bm_[4], bt_[4];
        #pragma unroll
        for (int j = 0; j < 4; j++) {
            int c = c0 + chunk * 8 + 2 * j;
            bm_[j] = packh(pm * normR, cm * normR);
            float m2 = fmaf(Km, cm, -pm);
            float m3 = fmaf(Km, m2, -cm);
            pm = m2; cm = m3;
            float na = (c == 0) ? n0 : n1;
            bt_[j] = packh(pt * na, ct * n1);
            float t2 = fmaf(Kt, ct, -pt);
            float t3 = fmaf(Kt, t2, -ct);
            pt = t2; ct = t3;
        }
        *(uint4*)(g_Dm + rowoff + c0 + chunk * 8) = *(uint4*)bm_;
        *(uint4*)(g_Dt + rowoff + c0 + chunk * 8) = *(uint4*)bt_;
    }
}

// ---------------------------------------------------------------------------
// fp32 -> fp16 converts (16 elems/thread; verified R13-R15 at 74% HBM)
// ---------------------------------------------------------------------------
static __device__ __forceinline__ void cvt16(const float* __restrict__ s,
                                             __half* __restrict__ d, int i)
{
    float4 v0 = *(const float4*)(s + i);
    float4 v1 = *(const float4*)(s + i + 4);
    float4 v2 = *(const float4*)(s + i + 8);
    float4 v3 = *(const float4*)(s + i + 12);
    uint4 b0, b1;
    b0.x = packh(v0.x, v0.y); b0.y = packh(v0.z, v0.w);
    b0.z = packh(v1.x, v1.y); b0.w = packh(v1.z, v1.w);
    b1.x = packh(v2.x, v2.y); b1.y = packh(v2.z, v2.w);
    b1.z = packh(v3.x, v3.y); b1.w = packh(v3.z, v3.w);
    *(uint4*)(d + i)     = b0;
    *(uint4*)(d + i + 8) = b1;
}

__global__ void convert_W1(const float* __restrict__ W1)
{
    int i = (blockIdx.x * blockDim.x + threadIdx.x) << 4;
    if (i < N1) cvt16(W1, g_W1f, i);
}

__global__ void convert_rest(const float* __restrict__ x,
                             const float* __restrict__ W2,
                             const float* __restrict__ Wmu,
                             const float* __restrict__ Wlv)
{
    int i = (blockIdx.x * blockDim.x + threadIdx.x) << 4;
    if (i < NX) {
        cvt16(x, g_x16, i);
    } else if (i < NX + N2) {
        cvt16(W2, g_W2f, i - NX);
    } else if (i < NX + N2 + N3) {
        cvt16(Wmu, g_Wmlf, i - NX - N2);
    } else if (i < NREST) {
        cvt16(Wlv, g_Wmlf + N3, i - NX - N2 - N3);
    }
}

// sum 2 split-K fp32 partials -> (optional colscale) -> fp16
__global__ void reduce2_f16(const float* __restrict__ part,
                            const float* __restrict__ colscale,
                            __half* __restrict__ dst, int n, int N)
{
    int i = (blockIdx.x * blockDim.x + threadIdx.x) << 2;
    if (i >= n) return;
    float4 a = *(const float4*)(part + i);
    float4 b = *(const float4*)(part + (size_t)n + i);
    float v0 = a.x + b.x;
    float v1 = a.y + b.y;
    float v2 = a.z + b.z;
    float v3 = a.w + b.w;
    if (colscale) {
        int col = i & (N - 1);
        v0 *= colscale[col];     v1 *= colscale[col + 1];
        v2 *= colscale[col + 2]; v3 *= colscale[col + 3];
    }
    uint2 buf;
    buf.x = packh(v0, v1);
    buf.y = packh(v2, v3);
    *(uint2*)(dst + i) = buf;
}

// ---------------------------------------------------------------------------
// mma.sync / ldmatrix / cp.async helpers
// ---------------------------------------------------------------------------
#define LDSM4(r0, r1, r2, r3, addr)                                            \
    asm volatile("ldmatrix.sync.aligned.m8n8.x4.shared.b16 {%0,%1,%2,%3}, [%4];" \
                 : "=r"(r0), "=r"(r1), "=r"(r2), "=r"(r3) : "r"(addr))

#define MMA_F16(c, a, b)                                                       \
    asm volatile("mma.sync.aligned.m16n8k16.row.col.f32.f16.f16.f32 "          \
                 "{%0,%1,%2,%3},{%4,%5,%6,%7},{%8,%9},{%0,%1,%2,%3};"          \
                 : "+f"((c)[0]), "+f"((c)[1]), "+f"((c)[2]), "+f"((c)[3])      \
                 : "r"((a)[0]), "r"((a)[1]), "r"((a)[2]), "r"((a)[3]),         \
                   "r"((b)[0]), "r"((b)[1]))

#define CP16(sa, ga)                                                           \
    asm volatile("cp.async.cg.shared.global [%0], [%1], 16;"                   \
                 :: "r"(sa), "l"(ga) : "memory")
#define CP_COMMIT() asm volatile("cp.async.commit_group;" ::: "memory")
#define CP_WAIT()   asm volatile("cp.async.wait_group %0;" :: "n"(NST - 2) : "memory")

// ---------------------------------------------------------------------------
// Pure fp16 NT GEMM (verified R11-R15; unchanged).
// ---------------------------------------------------------------------------
__global__ __launch_bounds__(256, 2)
void gemm_f16(const __half* __restrict__ Ap,
              const __half* __restrict__ Bp,
              const float* __restrict__ bias,
              __half* __restrict__ Cs,
              float* __restrict__ Cf,
              float* __restrict__ Cpart,
              int M, int N, int K, int klen, int do_relu)
{
    extern __shared__ __align__(1024) char smem[];
    const uint32_t sb = (uint32_t)__cvta_generic_to_shared(smem);

    const int tid   = threadIdx.x;
    const int lane  = tid & 31;
    const int wid   = tid >> 5;
    const int warpm = wid & 3;
    const int warpn = wid >> 2;
    const int bm = blockIdx.y * 128;
    const int bn = blockIdx.x * 128;
    const int kbase = blockIdx.z * klen;

    const uint32_t aOff = (uint32_t)(warpm * 32 + (lane & 15)) * ROWB
                        + (uint32_t)(lane >> 4) * 16u;
    const uint32_t bOff = (uint32_t)(warpn * 64 + (lane & 7) + ((lane & 16) ? 8 : 0)) * ROWB
                        + (uint32_t)((lane >> 3) & 1) * 16u;

    float acc[2][8][4];
    #pragma unroll
    for (int i = 0; i < 2; i++)
        #pragma unroll
        for (int j = 0; j < 8; j++)
            #pragma unroll
            for (int q = 0; q < 4; q++) acc[i][j][q] = 0.0f;

    const int nk = klen >> 6;

    auto issue_stage = [&](int kt) {
        const uint32_t base = sb + (uint32_t)(kt % NST) * STAGEB;
        const size_t kof = (size_t)kbase + (size_t)kt * BK;
        #pragma unroll
        for (int h = 0; h < 4; h++) {
            const int c   = tid + h * 256;
            const int row = c >> 3;
            const int q   = c & 7;
            const uint32_t so = (uint32_t)row * ROWB + (uint32_t)q * 16u;
            CP16(base + so,         Ap + (size_t)(bm + row) * K + kof + (size_t)q * 8);
            CP16(base + TILEB + so, Bp + (size_t)(bn + row) * K + kof + (size_t)q * 8);
        }
    };

    auto load_frags = [&](uint32_t base, uint32_t kb, uint32_t* F) {
        const uint32_t bT = base + TILEB;
        #pragma unroll
        for (int mf = 0; mf < 2; mf++) {
            uint32_t ad = base + aOff + (uint32_t)mf * (16u * ROWB) + kb;
            LDSM4(F[mf*4+0], F[mf*4+1], F[mf*4+2], F[mf*4+3], ad);
        }
        #pragma unroll
        for (int bf = 0; bf < 4; bf++) {
            uint32_t bd = bT + bOff + (uint32_t)bf * (16u * ROWB) + kb;
            LDSM4(F[8+bf*4+0], F[8+bf*4+1], F[8+bf*4+2], F[8+bf*4+3], bd);
        }
    };

    auto mma_step = [&](const uint32_t* F) {
        #pragma unroll
        for (int mf = 0; mf < 2; mf++)
            #pragma unroll
            for (int nf = 0; nf < 8; nf++) {
                const uint32_t* BF = &F[8 + (nf >> 1) * 4];
                uint32_t bb[2] = { BF[(nf & 1) ? 2 : 0], BF[(nf & 1) ? 3 : 1] };
                MMA_F16(acc[mf][nf], &F[mf * 4], bb);
            }
    };

    #pragma unroll
    for (int s = 0; s < NST - 1; s++) { issue_stage(s); CP_COMMIT(); }

    uint32_t F[24];

    for (int kt = 0; kt < nk; kt++) {
        CP_WAIT();
        __syncthreads();
        const uint32_t base = sb + (uint32_t)(kt % NST) * STAGEB;
        if (kt + NST - 1 < nk) issue_stage(kt + NST - 1);
        CP_COMMIT();
        #pragma unroll
        for (int ks = 0; ks < 4; ks++) {
            load_frags(base, (uint32_t)ks * 32u, F);
            mma_step(F);
        }
    }

    // ---- epilogue ----
    const int g  = lane >> 2;
    const int tg = lane & 3;
    #pragma unroll
    for (int mf = 0; mf < 2; mf++) {
        const int r0 = bm + warpm * 32 + mf * 16 + g;
        #pragma unroll
        for (int nf = 0; nf < 8; nf++) {
            const int col = bn + warpn * 64 + nf * 8 + tg * 2;
            float v0 = acc[mf][nf][0], v1 = acc[mf][nf][1];
            float v2 = acc[mf][nf][2], v3 = acc[mf][nf][3];

            if (Cpart) {   // split-K fp32 partial, plane = blockIdx.z
                float* base2 = Cpart + (size_t)blockIdx.z * ((size_t)M * N);
                *(float2*)(base2 + (size_t)r0 * N + col)       = make_float2(v0, v1);
                *(float2*)(base2 + (size_t)(r0 + 8) * N + col) = make_float2(v2, v3);
                continue;
            }
            float b0 = bias[col], b1 = bias[col + 1];
            v0 += b0; v1 += b1; v2 += b0; v3 += b1;
            if (do_relu) {
                v0 = fmaxf(v0, 0.0f); v1 = fmaxf(v1, 0.0f);
                v2 = fmaxf(v2, 0.0f); v3 = fmaxf(v3, 0.0f);
            }
            if (Cf) {      // final: N==512; cols [0,256) mu, [256,512) logvar
                float* p0;
                float* p1;
                if (col < 256) {
                    p0 = Cf + (size_t)r0 * 256 + col;
                    p1 = Cf + (size_t)(r0 + 8) * 256 + col;
                } else {
                    float* half2p = Cf + (size_t)BATCH * 256;
                    p0 = half2p + (size_t)r0 * 256 + (col - 256);
                    p1 = half2p + (size_t)(r0 + 8) * 256 + (col - 256);
                }
                *(float2*)p0 = make_float2(v0, v1);
                *(float2*)p1 = make_float2(v2, v3);
            } else {
                *(uint32_t*)(Cs + (size_t)r0 * N + col)       = packh(v0, v1);
                *(uint32_t*)(Cs + (size_t)(r0 + 8) * N + col) = packh(v2, v3);
            }
        }
    }
}

// ---------------------------------------------------------------------------
// Launch: forked-stream graph.
//   default: setup -> build_D -> cvtW1 -> A1 gemm -> red -> W1e gemm -> red
//   s2:      convert x/W2/Wmu/Wlv  (runs concurrently with weight chain)
//   join -> h1 -> h2 -> out
// ---------------------------------------------------------------------------
extern "C" void kernel_launch(void* const* d_in, const int* in_sizes, int n_in,
                              void* d_out, int out_size)
{
    const float* x   = (const float*)d_in[0];
    const float* fw  = (const float*)d_in[1];
    const float* kp  = (const float*)d_in[2];
    const float* W1  = (const float*)d_in[3];
    const float* b1  = (const float*)d_in[4];
    const float* W2  = (const float*)d_in[5];
    const float* b2  = (const float*)d_in[6];
    const float* Wmu = (const float*)d_in[7];
    const float* bmu = (const float*)d_in[8];
    const float* Wlv = (const float*)d_in[9];
    const float* blv = (const float*)d_in[10];
    float* out = (float*)d_out;

    __half *Dt, *Dm, *W1f, *A1f, *W1ef, *x16, *h1_16, *h2_16, *W2f, *Wmlf;
    float *bml, *bscale, *part;
    cudaGetSymbolAddress((void**)&Dt,    g_Dt);
    cudaGetSymbolAddress((void**)&Dm,    g_Dm);
    cudaGetSymbolAddress((void**)&W1f,   g_W1f);
    cudaGetSymbolAddress((void**)&A1f,   g_A1f);
    cudaGetSymbolAddress((void**)&W1ef,  g_W1ef);
    cudaGetSymbolAddress((void**)&x16,   g_x16);
    cudaGetSymbolAddress((void**)&h1_16, g_h1_16);
    cudaGetSymbolAddress((void**)&h2_16, g_h2_16);
    cudaGetSymbolAddress((void**)&W2f,   g_W2f);
    cudaGetSymbolAddress((void**)&Wmlf,  g_Wmlf);
    cudaGetSymbolAddress((void**)&bml,   g_bml);
    cudaGetSymbolAddress((void**)&bscale, g_bscale);
    cudaGetSymbolAddress((void**)&part,  g_part);

    cudaFuncSetAttribute(gemm_f16,
                         cudaFuncAttributeMaxDynamicSharedMemorySize, SMEM_GEMM);

    // Fork resources (host-side; no device memory). Leaked intentionally —
    // kernel_launch is invoked only a handful of times (correctness+capture).
    cudaStream_t s2;
    cudaEvent_t evFork, evJoin;
    cudaStreamCreateWithFlags(&s2, cudaStreamNonBlocking);
    cudaEventCreateWithFlags(&evFork, cudaEventDisableTiming);
    cudaEventCreateWithFlags(&evJoin, cudaEventDisableTiming);

    // ---- fork ----
    cudaEventRecord(evFork, 0);
    cudaStreamWaitEvent(s2, evFork, 0);

    // s2: big memory-bound converts (x, W2, Wmu, Wlv)
    convert_rest<<<(NREST / 16 + 255) / 256, 256, 0, s2>>>(x, W2, Wmu, Wlv);
    cudaEventRecord(evJoin, s2);

    // default stream: setup + D build + weight-prep chain
    setup_kernel<<<42, 256>>>(fw, kp, bmu, blv);
    build_D_kernel<<<(DIMN * 64) / 256, 256>>>();
    convert_W1<<<(N1 / 16 + 255) / 256, 256>>>(W1);

    const int nW = 1024 * DIMN;

    // A1[j][kf] = (sum_n W1[j][n] * Dm[kf][n]) * bscale[kf]  (split-K=2)
    gemm_f16<<<dim3(16, 8, 2), 256, SMEM_GEMM>>>(
        W1f, Dm, nullptr, nullptr, nullptr, part, 1024, 2048, 2048, 1024, 0);
    reduce2_f16<<<(nW / 4 + 255) / 256, 256>>>(part, bscale, A1f, nW, 2048);

    // W1e[j][m] = sum_kf A1[j][kf] * Dt[m][kf]               (split-K=2)
    gemm_f16<<<dim3(16, 8, 2), 256, SMEM_GEMM>>>(
        A1f, Dt, nullptr, nullptr, nullptr, part, 1024, 2048, 2048, 1024, 0);
    reduce2_f16<<<(nW / 4 + 255) / 256, 256>>>(part, nullptr, W1ef, nW, 2048);

    // ---- join: batch GEMMs need both chains ----
    cudaStreamWaitEvent(0, evJoin, 0);

    // h1 = relu(x @ W1e^T + b1)
    gemm_f16<<<dim3(8, 128, 1), 256, SMEM_GEMM>>>(
        x16, W1ef, b1, h1_16, nullptr, nullptr, BATCH, 1024, 2048, 2048, 1);
    // h2 = relu(h1 @ W2^T + b2)
    gemm_f16<<<dim3(4, 128, 1), 256, SMEM_GEMM>>>(
        h1_16, W2f, b2, h2_16, nullptr, nullptr, BATCH, 512, 1024, 1024, 1);
    // [mu | logvar] = h2 @ [Wmu;Wlv]^T + [bmu;blv]
    gemm_f16<<<dim3(4, 128, 1), 256, SMEM_GEMM>>>(
        h2_16, Wmlf, bml, nullptr, out, nullptr, BATCH, 512, 512, 512, 0);
}